// round 5
// baseline (speedup 1.0000x reference)
#include <cuda_runtime.h>

// out[(b*H+h)*(N+1)^2 + r*(N+1) + c] =
//   token[h]                                  if r==0 || c==0
//   emb[spatial_types[b*N*N + (r-1)*N + (c-1)] * H + h]  otherwise
//
// One thread per (b, r, c); each thread writes H=8 floats (one per h-plane).
// Consecutive threads -> consecutive c -> coalesced 128B stores per plane and
// coalesced spatial_types loads. emb_weight + graph_token staged in smem.

__global__ void wbe_kernel_h8(const int* __restrict__ st,
                              const float* __restrict__ emb,
                              const float* __restrict__ token,
                              float* __restrict__ out,
                              int B, int N, int embRows, long long total)
{
    extern __shared__ float sh[];            // embRows*8 floats, then 8 token floats
    float* s_emb = sh;
    float* s_tok = sh + (size_t)embRows * 8; // 16B-aligned (embRows*8*4 % 16 == 0)

    const int nsh = embRows * 8;
    for (int i = threadIdx.x; i < nsh; i += blockDim.x) s_emb[i] = emb[i];
    if (threadIdx.x < 8) s_tok[threadIdx.x] = token[threadIdx.x];
    __syncthreads();

    long long idx = (long long)blockIdx.x * blockDim.x + threadIdx.x;
    if (idx >= total) return;

    const int Np1 = N + 1;
    int c = (int)(idx % Np1);
    long long t = idx / Np1;
    int r = (int)(t % Np1);
    int b = (int)(t / Np1);

    const float4* src4;
    if (r == 0 || c == 0) {
        src4 = reinterpret_cast<const float4*>(s_tok);
    } else {
        int stv = __ldg(&st[((long long)b * N + (r - 1)) * N + (c - 1)]);
        src4 = reinterpret_cast<const float4*>(s_emb + (size_t)stv * 8);
    }
    float4 v0 = src4[0];
    float4 v1 = src4[1];
    float vals[8] = {v0.x, v0.y, v0.z, v0.w, v1.x, v1.y, v1.z, v1.w};

    const long long plane = (long long)Np1 * Np1;
    long long o = ((long long)b * 8) * plane + (long long)r * Np1 + c;
    #pragma unroll
    for (int h = 0; h < 8; ++h)
        out[o + (long long)h * plane] = vals[h];
}

// Generic-H fallback (correctness safety net; not expected to run for this bench)
__global__ void wbe_kernel_generic(const int* __restrict__ st,
                                   const float* __restrict__ emb,
                                   const float* __restrict__ token,
                                   float* __restrict__ out,
                                   int B, int N, int H, int embRows,
                                   long long total)
{
    extern __shared__ float sh[];
    float* s_emb = sh;
    float* s_tok = sh + (size_t)embRows * H;
    const int nsh = embRows * H;
    for (int i = threadIdx.x; i < nsh; i += blockDim.x) s_emb[i] = emb[i];
    for (int i = threadIdx.x; i < H; i += blockDim.x) s_tok[i] = token[i];
    __syncthreads();

    long long idx = (long long)blockIdx.x * blockDim.x + threadIdx.x;
    if (idx >= total) return;

    const int Np1 = N + 1;
    int c = (int)(idx % Np1);
    long long t = idx / Np1;
    int r = (int)(t % Np1);
    int b = (int)(t / Np1);

    const float* src;
    if (r == 0 || c == 0) {
        src = s_tok;
    } else {
        int stv = __ldg(&st[((long long)b * N + (r - 1)) * N + (c - 1)]);
        src = s_emb + (size_t)stv * H;
    }
    const long long plane = (long long)Np1 * Np1;
    long long o = ((long long)b * H) * plane + (long long)r * Np1 + c;
    for (int h = 0; h < H; ++h)
        out[o + (long long)h * plane] = src[h];
}

extern "C" void kernel_launch(void* const* d_in, const int* in_sizes, int n_in,
                              void* d_out, int out_size)
{
    // metadata order:
    // 0: spatial_types [E] int32
    // 1: graph_index   [2,E] int32   (structure implied; not needed)
    // 2: batch         [num_nodes] int32
    // 3: num_graphs    (scalar)
    // 4: max_nodes     (scalar)
    // 5: emb_weight    [(S+1), H] float32
    // 6: graph_token   [1, H, 1] float32
    const int*   st    = (const int*)  d_in[0];
    const float* emb   = (const float*)d_in[5];
    const float* token = (const float*)d_in[6];
    float* out = (float*)d_out;

    const long long E = in_sizes[0];
    const int num_nodes = in_sizes[2];
    const int H = in_sizes[6];
    const int embRows = in_sizes[5] / H;
    const int N = (int)(E / num_nodes);   // E = B*N*N, num_nodes = B*N
    const int B = num_nodes / N;

    const long long Np1 = N + 1;
    const long long total = (long long)B * Np1 * Np1;

    const int threads = 256;
    const long long blocks = (total + threads - 1) / threads;
    const size_t smem = ((size_t)embRows * H + H) * sizeof(float);

    if (H == 8) {
        wbe_kernel_h8<<<(unsigned)blocks, threads, smem>>>(
            st, emb, token, out, B, N, embRows, total);
    } else {
        wbe_kernel_generic<<<(unsigned)blocks, threads, smem>>>(
            st, emb, token, out, B, N, H, embRows, total);
    }
}

// round 8
// speedup vs baseline: 1.1848x; 1.1848x over previous
#include <cuda_runtime.h>

// out[(b*8+h)*Np1^2 + r*Np1 + c] =
//   token[h]                                   if r==0 || c==0
//   emb[ st[(b*N + (r-1))*N + (c-1)] ][h]      otherwise
//
// Block (512 thr = 16 warps) handles TWO output rows (b,r).
// Warp w: h = w&7, row-slot k = w>>3. Lanes sweep c with stride 32.
// emb staged transposed in smem (odd pitch -> uniform banks for random s),
// st row staged in smem (stride-1 reads -> conflict-free).
// No 64-bit arithmetic anywhere (out has 33.7M < 2^31 elements).

__global__ void __launch_bounds__(512)
wbe_h8_rows(const int* __restrict__ st,
            const float* __restrict__ emb,
            const float* __restrict__ token,
            float* __restrict__ out,
            int B, int N, int embRows, int pitch)
{
    extern __shared__ float sh[];
    float* s_embT = sh;                       // 8 * pitch floats
    float* s_tok  = sh + 8 * pitch;           // 8 floats
    int*   s_st   = (int*)(s_tok + 8);        // 2 * N ints

    const int tid = threadIdx.x;
    const int Np1 = N + 1;
    const int plane = Np1 * Np1;
    const int totalRows = B * Np1;

    // Stage emb transposed: s_embT[h*pitch + s] = emb[s*8 + h]
    for (int i = tid; i < embRows * 8; i += blockDim.x) {
        int s = i >> 3, h = i & 7;
        s_embT[h * pitch + s] = emb[i];
    }
    if (tid < 8) s_tok[tid] = token[tid];

    // Stage st for both rows of this block
    const int rid0 = blockIdx.x * 2;
    int base0 = -1, base1 = -1;
    {
        int rid = rid0;
        if (rid < totalRows) {
            int b = rid / Np1;
            int r = rid - b * Np1;
            if (r >= 1) base0 = (b * N + (r - 1)) * N;
        }
        rid = rid0 + 1;
        if (rid < totalRows) {
            int b = rid / Np1;
            int r = rid - b * Np1;
            if (r >= 1) base1 = (b * N + (r - 1)) * N;
        }
    }
    for (int j = tid; j < N; j += blockDim.x) {
        if (base0 >= 0) s_st[j]     = st[base0 + j];
        if (base1 >= 0) s_st[N + j] = st[base1 + j];
    }
    __syncthreads();

    const int w    = tid >> 5;
    const int lane = tid & 31;
    const int h    = w & 7;
    const int k    = w >> 3;

    const int rid = rid0 + k;
    if (rid >= totalRows) return;
    const int b = rid / Np1;
    const int r = rid - b * Np1;

    const float tokv = s_tok[h];
    const float* __restrict__ erow  = s_embT + h * pitch;
    const int*   __restrict__ strow = s_st + k * N;
    const int obase = (b * 8 + h) * plane + r * Np1;

    if (r == 0) {
        // whole row is the graph token
        for (int c = lane; c < Np1; c += 32)
            out[obase + c] = tokv;
    } else {
        if (lane == 0) out[obase] = tokv;     // c == 0 token column
        #pragma unroll 4
        for (int c = lane + 1; c < Np1; c += 32) {
            int s = strow[c - 1];             // stride-1 LDS, conflict-free
            out[obase + c] = erow[s];         // uniform-bank LDS gather
        }
    }
}

// Generic-H fallback (safety net; not expected for this bench)
__global__ void wbe_kernel_generic(const int* __restrict__ st,
                                   const float* __restrict__ emb,
                                   const float* __restrict__ token,
                                   float* __restrict__ out,
                                   int B, int N, int H, int embRows,
                                   long long total)
{
    extern __shared__ float sh[];
    float* s_emb = sh;
    float* s_tok = sh + (size_t)embRows * H;
    const int nsh = embRows * H;
    for (int i = threadIdx.x; i < nsh; i += blockDim.x) s_emb[i] = emb[i];
    for (int i = threadIdx.x; i < H; i += blockDim.x) s_tok[i] = token[i];
    __syncthreads();

    long long idx = (long long)blockIdx.x * blockDim.x + threadIdx.x;
    if (idx >= total) return;

    const int Np1 = N + 1;
    int c = (int)(idx % Np1);
    long long t = idx / Np1;
    int r = (int)(t % Np1);
    int bb = (int)(t / Np1);

    const float* src;
    if (r == 0 || c == 0) {
        src = s_tok;
    } else {
        int stv = st[((long long)bb * N + (r - 1)) * N + (c - 1)];
        src = s_emb + (size_t)stv * H;
    }
    const long long plane = (long long)Np1 * Np1;
    long long o = ((long long)bb * H) * plane + (long long)r * Np1 + c;
    for (int hh = 0; hh < H; ++hh)
        out[o + (long long)hh * plane] = src[hh];
}

extern "C" void kernel_launch(void* const* d_in, const int* in_sizes, int n_in,
                              void* d_out, int out_size)
{
    // inputs (metadata order):
    // 0: spatial_types [E] int32, 1: graph_index [2,E] int32, 2: batch [B*N] int32,
    // 3: num_graphs, 4: max_nodes, 5: emb_weight [(S+1),H] f32, 6: graph_token [1,H,1] f32
    const int*   st    = (const int*)  d_in[0];
    const float* emb   = (const float*)d_in[5];
    const float* token = (const float*)d_in[6];
    float* out = (float*)d_out;

    const long long E = in_sizes[0];
    const int num_nodes = in_sizes[2];
    const int H = in_sizes[6];
    const int embRows = in_sizes[5] / H;
    const int N = (int)(E / num_nodes);   // E = B*N*N, num_nodes = B*N
    const int B = num_nodes / N;
    const int Np1 = N + 1;

    if (H == 8 && (long long)B * H * Np1 * Np1 < (1LL << 31)) {
        const int pitch = (embRows & 1) ? embRows : embRows + 1;  // odd -> uniform banks
        const int totalRows = B * Np1;
        const int blocks = (totalRows + 1) / 2;
        const size_t smem = (size_t)(8 * pitch + 8) * sizeof(float)
                          + (size_t)(2 * N) * sizeof(int);
        wbe_h8_rows<<<blocks, 512, smem>>>(st, emb, token, out, B, N, embRows, pitch);
    } else {
        const long long total = (long long)B * Np1 * Np1;
        const int threads = 256;
        const long long blocks = (total + threads - 1) / threads;
        const size_t smem = ((size_t)embRows * H + H) * sizeof(float);
        wbe_kernel_generic<<<(unsigned)blocks, threads, smem>>>(
            st, emb, token, out, B, N, H, embRows, total);
    }
}